// round 5
// baseline (speedup 1.0000x reference)
#include <cuda_runtime.h>
#include <cuda_bf16.h>
#include <math.h>

#define A_TOT 147456      // 128*128*9 anchors
#define HW    16384
#define GW    128
#define CIN   512
#define KTOT  4608        // 512*9
#define NCOL  1280        // 128*4 (pos bbox) + 128*2 (pos score) + 256*2 (neg score)
#define STEP  (2048.0f/127.0f)

// anchor width/height table (area x ratio, matches reference order)
__constant__ float d_whw[9] = {128.0f, 181.01933598375618f, 90.50966799187809f,
                               256.0f, 362.03867196751236f, 181.01933598375618f,
                               512.0f, 724.0773439350247f, 362.03867196751236f};
__constant__ float d_whh[9] = {128.0f, 90.50966799187809f, 181.01933598375618f,
                               256.0f, 181.01933598375618f, 362.03867196751236f,
                               512.0f, 362.03867196751236f, 724.0773439350247f};

// ---------------- static device scratch (no allocations allowed) ----------------
__device__ float              d_maxIou[A_TOT];
__device__ int                d_tgtIdx[A_TOT];
__device__ unsigned long long d_keyPos[A_TOT];
__device__ unsigned long long d_keyNeg[A_TOT];
__device__ unsigned long long d_candPos[72 * 256];
__device__ unsigned long long d_candNeg[72 * 256];
__device__ unsigned long long d_sortPos[256];
__device__ unsigned long long d_sortNeg[256];
__device__ int                d_posIdx[128];
__device__ int                d_posValid[128];
__device__ int                d_negIdx[256];
__device__ int                d_negValid[256];
__device__ int                d_nPos;
__device__ int                d_colPos[NCOL];   // spatial position per GEMM column
__device__ int                d_colMeta[NCOL];  // 0..35 bbox chan, 36..53 score chan+36
__device__ float              d_Bg[KTOT * NCOL];  // gathered patches  (23.6 MB)
__device__ float              d_h[CIN * NCOL];    // hidden activations (2.6 MB)
__device__ float              d_val[NCOL];        // final per-column conv outputs

// ---------------- phase A: IoU matching + key build ----------------
__global__ void iou_kernel(const float* __restrict__ target) {
    __shared__ float4 tg[64];
    int t = threadIdx.x;
    if (t < 64) tg[t] = ((const float4*)target)[t];
    __syncthreads();
    int a = blockIdx.x * 256 + t;            // grid 576*256 == A_TOT exactly
    int k = a % 9;
    int q = a / 9;
    int wq = q & 127;                        // -> y uses ys[w]
    int hq = q >> 7;                         // -> x uses xs[h]
    float x1 = hq * STEP;
    float y1 = wq * STEP;
    float x2 = x1 + d_whw[k];
    float y2 = y1 + d_whh[k];
    float areaA = (x2 - x1) * (y2 - y1);

    float best = -1.0f;
    int bi = 0;
    #pragma unroll 4
    for (int i = 0; i < 64; i++) {
        float4 b = tg[i];
        float lx = fmaxf(b.x, x1), ly = fmaxf(b.y, y1);
        float rx = fminf(b.z, x2), ry = fminf(b.w, y2);
        float iw = fmaxf(rx - lx, 0.0f), ih = fmaxf(ry - ly, 0.0f);
        float inter = iw * ih;
        float at = (b.z - b.x) * (b.w - b.y);
        float iou = inter / (at + areaA - inter);
        if (iou > best) { best = iou; bi = i; }   // first-max == jnp.argmax
    }
    d_maxIou[a] = best;
    d_tgtIdx[a] = bi;
    unsigned ui = 0xFFFFFFFFu - (unsigned)a;      // ties -> lower index wins
    d_keyPos[a] = (best > 0.7f)
        ? (((unsigned long long)__float_as_uint(best) << 32) | ui) : 0ULL;
    float nv = 1.0f - best;
    d_keyNeg[a] = (best < 0.3f)
        ? (((unsigned long long)__float_as_uint(nv) << 32) | ui) : 0ULL;
}

// ---------------- exact top-k: two-level bitonic ----------------
__device__ __forceinline__ void bitonic2048(unsigned long long* s) {
    int t = threadIdx.x;  // 1024 threads
    for (int k = 2; k <= 2048; k <<= 1) {
        for (int j = k >> 1; j > 0; j >>= 1) {
            __syncthreads();
            #pragma unroll
            for (int base = 0; base < 2048; base += 1024) {
                int i = base + t;
                int ixj = i ^ j;
                if (ixj > i) {
                    unsigned long long va = s[i], vb = s[ixj];
                    bool sw = ((i & k) == 0) ? (va < vb) : (va > vb);  // descending
                    if (sw) { s[i] = vb; s[ixj] = va; }
                }
            }
        }
    }
    __syncthreads();
}

__global__ void topk_l1(int which) {  // 72 blocks x 1024 thr, 2048 keys/block
    __shared__ unsigned long long s[2048];
    const unsigned long long* keys = which ? d_keyNeg : d_keyPos;
    unsigned long long* cand = which ? d_candNeg : d_candPos;
    int t = threadIdx.x;
    int base = blockIdx.x * 2048;
    s[t] = keys[base + t];
    s[t + 1024] = keys[base + 1024 + t];
    __syncthreads();
    bitonic2048(s);
    if (t < 256) cand[blockIdx.x * 256 + t] = s[t];
}

__global__ void topk_l2(int which) {  // 1 block x 1024, merges 72*256=18432
    __shared__ unsigned long long s[2048];
    __shared__ unsigned long long best[256];
    const unsigned long long* cand = which ? d_candNeg : d_candPos;
    unsigned long long* out = which ? d_sortNeg : d_sortPos;
    const int count = 72 * 256;
    int t = threadIdx.x;
    s[t] = cand[t];
    s[t + 1024] = cand[t + 1024];
    __syncthreads();
    bitonic2048(s);
    if (t < 256) best[t] = s[t];
    __syncthreads();
    for (int base = 2048; base < count; base += 1792) {
        int i = base + t;
        s[t] = (i < count) ? cand[i] : 0ULL;
        int u = t + 1024;
        unsigned long long v;
        if (u < 1792) { int idx = base + u; v = (idx < count) ? cand[idx] : 0ULL; }
        else v = best[u - 1792];
        s[u] = v;
        __syncthreads();
        bitonic2048(s);
        if (t < 256) best[t] = s[t];
        __syncthreads();
    }
    if (t < 256) out[t] = best[t];
}

// ---------------- assemble column map ----------------
__global__ void assemble_kernel() {
    __shared__ int sh_npos;
    int t = threadIdx.x;
    if (t == 0) {
        int c = 0;
        for (int i = 0; i < 128; i++) if (d_sortPos[i] != 0ULL) c++;
        d_nPos = c;
        sh_npos = c;
    }
    __syncthreads();
    int npos = sh_npos;
    if (t < 128) {
        unsigned long long key = d_sortPos[t];
        int valid = (key != 0ULL);
        int p = valid ? (int)(0xFFFFFFFFu - (unsigned)(key & 0xFFFFFFFFULL)) : 0;
        d_posIdx[t] = p;
        d_posValid[t] = valid;
        int sb = (4 * p) & 16383;       // bbox row spatial base (channel p>>12)
        int ss = (2 * p) & 16383;       // score row spatial base (channel p>>13)
        int cb = valid ? (p >> 12) : 0;
        int cs = valid ? (36 + (p >> 13)) : 36;
        #pragma unroll
        for (int e = 0; e < 4; e++) {
            d_colPos[4 * t + e] = valid ? (sb + e) : 0;
            d_colMeta[4 * t + e] = cb;
        }
        #pragma unroll
        for (int e = 0; e < 2; e++) {
            d_colPos[512 + 2 * t + e] = valid ? (ss + e) : 0;
            d_colMeta[512 + 2 * t + e] = cs;
        }
    }
    if (t < 256) {
        unsigned long long key = d_sortNeg[t];
        int valid = (key != 0ULL) && (t < 256 - npos);   // slot-position mask!
        int n = valid ? (int)(0xFFFFFFFFu - (unsigned)(key & 0xFFFFFFFFULL)) : 0;
        d_negIdx[t] = n;
        d_negValid[t] = valid;
        int ss = (2 * n) & 16383;
        int cs = valid ? (36 + (n >> 13)) : 36;
        #pragma unroll
        for (int e = 0; e < 2; e++) {
            d_colPos[768 + 2 * t + e] = valid ? (ss + e) : 0;
            d_colMeta[768 + 2 * t + e] = cs;
        }
    }
}

// ---------------- gather 3x3 input patches: Bg[k][n] ----------------
__global__ void gather_kernel(const float* __restrict__ x) {
    int idx = blockIdx.x * 256 + threadIdx.x;   // grid 23040*256 == KTOT*NCOL
    int n = idx % NCOL;
    int k = idx / NCOL;
    int s = d_colPos[n];
    int ci = k / 9;
    int r  = k - ci * 9;
    int ky = r / 3;
    int kx = r - ky * 3;
    int y  = (s >> 7) + ky - 1;
    int xx = (s & 127) + kx - 1;
    float v = 0.0f;
    if (((unsigned)y < 128u) && ((unsigned)xx < 128u))
        v = x[ci * HW + y * GW + xx];
    d_Bg[idx] = v;
}

// ---------------- GEMM: h[512][1280] = relu(W[512][4608] @ Bg + b) ----------------
__global__ __launch_bounds__(256, 2)
void gemm_kernel(const float* __restrict__ W, const float* __restrict__ bias) {
    __shared__ float As[16][68];   // padded (bank conflicts, 16B-aligned rows)
    __shared__ float Bs[16][64];
    int tid = threadIdx.x;
    int tx = tid & 15, ty = tid >> 4;
    int m0 = blockIdx.y * 64, n0 = blockIdx.x * 64;

    int aRow = tid >> 2;               // 0..63
    int aK4  = (tid & 3) << 2;         // 0,4,8,12
    int bK   = tid >> 4;               // 0..15
    int bN4  = (tid & 15) << 2;        // 0..60
    const float* Ap = W + (m0 + aRow) * KTOT + aK4;
    const float* Bp = d_Bg + bK * NCOL + n0 + bN4;

    float acc[4][4];
    #pragma unroll
    for (int i = 0; i < 4; i++)
        #pragma unroll
        for (int j = 0; j < 4; j++) acc[i][j] = 0.0f;

    for (int k0 = 0; k0 < KTOT; k0 += 16) {
        float4 av = *(const float4*)(Ap + k0);
        float4 bv = *(const float4*)(Bp + k0 * NCOL);
        __syncthreads();
        As[aK4 + 0][aRow] = av.x;
        As[aK4 + 1][aRow] = av.y;
        As[aK4 + 2][aRow] = av.z;
        As[aK4 + 3][aRow] = av.w;
        *(float4*)&Bs[bK][bN4] = bv;
        __syncthreads();
        #pragma unroll
        for (int kk = 0; kk < 16; kk++) {
            float4 a = *(const float4*)&As[kk][ty << 2];
            float4 b = *(const float4*)&Bs[kk][tx << 2];
            acc[0][0] = fmaf(a.x, b.x, acc[0][0]);
            acc[0][1] = fmaf(a.x, b.y, acc[0][1]);
            acc[0][2] = fmaf(a.x, b.z, acc[0][2]);
            acc[0][3] = fmaf(a.x, b.w, acc[0][3]);
            acc[1][0] = fmaf(a.y, b.x, acc[1][0]);
            acc[1][1] = fmaf(a.y, b.y, acc[1][1]);
            acc[1][2] = fmaf(a.y, b.z, acc[1][2]);
            acc[1][3] = fmaf(a.y, b.w, acc[1][3]);
            acc[2][0] = fmaf(a.z, b.x, acc[2][0]);
            acc[2][1] = fmaf(a.z, b.y, acc[2][1]);
            acc[2][2] = fmaf(a.z, b.z, acc[2][2]);
            acc[2][3] = fmaf(a.z, b.w, acc[2][3]);
            acc[3][0] = fmaf(a.w, b.x, acc[3][0]);
            acc[3][1] = fmaf(a.w, b.y, acc[3][1]);
            acc[3][2] = fmaf(a.w, b.z, acc[3][2]);
            acc[3][3] = fmaf(a.w, b.w, acc[3][3]);
        }
    }
    #pragma unroll
    for (int i = 0; i < 4; i++) {
        int m = m0 + (ty << 2) + i;
        float bi = bias[m];
        float4 o;
        o.x = fmaxf(acc[i][0] + bi, 0.0f);
        o.y = fmaxf(acc[i][1] + bi, 0.0f);
        o.z = fmaxf(acc[i][2] + bi, 0.0f);
        o.w = fmaxf(acc[i][3] + bi, 0.0f);
        *(float4*)&d_h[m * NCOL + n0 + (tx << 2)] = o;
    }
}

// ---------------- per-column 1x1 conv (one selected channel per column) ----------------
__global__ void coldot_kernel(const float* __restrict__ bw, const float* __restrict__ bb,
                              const float* __restrict__ sw, const float* __restrict__ sb) {
    int gwp = blockIdx.x * 8 + (threadIdx.x >> 5);   // 160 blocks * 8 warps = 1280
    int lane = threadIdx.x & 31;
    int meta = d_colMeta[gwp];
    const float* w;
    float b;
    if (meta < 36) { w = bw + meta * 512; b = bb[meta]; }
    else           { w = sw + (meta - 36) * 512; b = sb[meta - 36]; }
    float s = 0.0f;
    #pragma unroll
    for (int c = lane; c < 512; c += 32) s = fmaf(w[c], d_h[c * NCOL + gwp], s);
    #pragma unroll
    for (int o = 16; o > 0; o >>= 1) s += __shfl_xor_sync(0xFFFFFFFFu, s, o);
    if (lane == 0) d_val[gwp] = fmaxf(s + b, 0.0f);
}

// ---------------- loss ----------------
__global__ void loss_kernel(const float* __restrict__ target, float* __restrict__ out) {
    __shared__ float rce[256], rsl[256], rvc[256];
    int t = threadIdx.x;
    float ce = 0.0f, sl = 0.0f, vc = 0.0f;
    if (t < 128 && d_posValid[t]) {
        float s0 = d_val[512 + 2 * t], s1 = d_val[512 + 2 * t + 1];
        float m = fmaxf(s0, s1);
        float lse = m + logf(expf(s0 - m) + expf(s1 - m));
        ce += lse - s0;           // target [1,0]
        vc += 1.0f;
        int p = d_posIdx[t];
        int k = p % 9;
        int q = p / 9;
        int wq = q & 127;
        int hq = q >> 7;
        float ax1 = hq * STEP, ay1 = wq * STEP;
        float ax2 = ax1 + d_whw[k], ay2 = ay1 + d_whh[k];
        float aw = ax2 - ax1, ah = ay2 - ay1;
        float acx = ax1 + aw * 0.5f, acy = ay1 + ah * 0.5f;
        float4 tb = ((const float4*)target)[d_tgtIdx[p]];
        float bw_ = tb.z - tb.x, bh_ = tb.w - tb.y;
        float bcx = tb.x + bw_ * 0.5f, bcy = tb.y + bh_ * 0.5f;
        float tr0 = (bcx - acx) / aw;
        float tr1 = (bcy - acy) / ah;
        float tr2 = logf(bw_ / aw);
        float tr3 = logf(bh_ / ah);
        float tr[4] = {tr0, tr1, tr2, tr3};
        #pragma unroll
        for (int e = 0; e < 4; e++) {
            float d = d_val[4 * t + e] - tr[e];
            float ad = fabsf(d);
            sl += (ad < 1.0f) ? 0.5f * d * d : (ad - 0.5f);
        }
    }
    if (t < 256 && d_negValid[t]) {
        float s0 = d_val[768 + 2 * t], s1 = d_val[768 + 2 * t + 1];
        float m = fmaxf(s0, s1);
        float lse = m + logf(expf(s0 - m) + expf(s1 - m));
        ce += lse - s1;           // target [0,1]
        vc += 1.0f;
    }
    rce[t] = ce; rsl[t] = sl; rvc[t] = vc;
    __syncthreads();
    for (int s2 = 128; s2 > 0; s2 >>= 1) {
        if (t < s2) { rce[t] += rce[t + s2]; rsl[t] += rsl[t + s2]; rvc[t] += rvc[t + s2]; }
        __syncthreads();
    }
    if (t == 0) {
        float np = (float)d_nPos;
        float score_loss = rce[0] / fmaxf(rvc[0], 1.0f);
        float reg_loss = rsl[0] / fmaxf(np * 4.0f, 1.0f);
        out[0] = score_loss + 10.0f * reg_loss;
    }
}

// ---------------- launch ----------------
extern "C" void kernel_launch(void* const* d_in, const int* in_sizes, int n_in,
                              void* d_out, int out_size) {
    const float* x       = (const float*)d_in[0];
    const float* target  = (const float*)d_in[1];
    const float* conv_w  = (const float*)d_in[2];
    const float* conv_b  = (const float*)d_in[3];
    const float* bbox_w  = (const float*)d_in[4];
    const float* bbox_b  = (const float*)d_in[5];
    const float* score_w = (const float*)d_in[6];
    const float* score_b = (const float*)d_in[7];
    float* out = (float*)d_out;

    iou_kernel<<<A_TOT / 256, 256>>>(target);
    topk_l1<<<72, 1024>>>(0);
    topk_l1<<<72, 1024>>>(1);
    topk_l2<<<1, 1024>>>(0);
    topk_l2<<<1, 1024>>>(1);
    assemble_kernel<<<1, 256>>>();
    gather_kernel<<<(KTOT * NCOL) / 256, 256>>>(x);
    gemm_kernel<<<dim3(NCOL / 64, CIN / 64), 256>>>(conv_w, conv_b);
    coldot_kernel<<<NCOL / 8, 256>>>(bbox_w, bbox_b, score_w, score_b);
    loss_kernel<<<1, 256>>>(target, out);
}

// round 6
// speedup vs baseline: 2.2700x; 2.2700x over previous
#include <cuda_runtime.h>
#include <cuda_bf16.h>
#include <math.h>

#define A_TOT 147456      // 128*128*9 anchors
#define HW    16384
#define GW    128
#define CIN   512
#define KTOT  4608        // 512*9
#define KSPLIT 4
#define KCH   1152        // KTOT/KSPLIT
#define NCOL  1280        // 128*4 (pos bbox) + 128*2 (pos score) + 256*2 (neg score)
#define NBLK  576         // A_TOT/256
#define STEP  (2048.0f/127.0f)

__constant__ float d_whw[9] = {128.0f, 181.01933598375618f, 90.50966799187809f,
                               256.0f, 362.03867196751236f, 181.01933598375618f,
                               512.0f, 724.0773439350247f, 362.03867196751236f};
__constant__ float d_whh[9] = {128.0f, 90.50966799187809f, 181.01933598375618f,
                               256.0f, 181.01933598375618f, 362.03867196751236f,
                               512.0f, 362.03867196751236f, 724.0773439350247f};

// ---------------- static device scratch ----------------
__device__ float d_maxIou[A_TOT];
__device__ int   d_tgtIdx[A_TOT];
__device__ int   d_zCnt[NBLK];
__device__ int   d_pCnt[NBLK];
__device__ int   d_zPrefix[NBLK];
__device__ int   d_pPrefix[NBLK];
__device__ int   d_posTotal;
__device__ int   d_posIdx[128];
__device__ int   d_posValid[128];
__device__ int   d_negIdx[256];
__device__ int   d_negValid[256];
__device__ int   d_nPos;
__device__ int   d_colPos[NCOL];
__device__ int   d_colMeta[NCOL];
__device__ float d_Bg[KTOT * NCOL];        // gathered patches, [k][n]
__device__ float d_hp[KSPLIT * NCOL * CIN]; // GEMM partials, [ks][n][m]
__device__ float d_hT[NCOL * CIN];          // hidden transposed, [n][c]
__device__ float d_val[NCOL];

// ---------------- packed fp32 FMA ----------------
__device__ __forceinline__ unsigned long long ffma2(unsigned long long a,
                                                    unsigned long long b,
                                                    unsigned long long c) {
    unsigned long long d;
    asm("fma.rn.f32x2 %0, %1, %2, %3;" : "=l"(d) : "l"(a), "l"(b), "l"(c));
    return d;
}

// ---------------- phase A: IoU matching + per-block class counts ----------------
__global__ void iou_kernel(const float* __restrict__ target) {
    __shared__ float4 tg[64];
    __shared__ int wz[8], wp[8];
    int t = threadIdx.x;
    if (t < 64) tg[t] = ((const float4*)target)[t];
    __syncthreads();
    int a = blockIdx.x * 256 + t;
    int k = a % 9;
    int q = a / 9;
    int wq = q & 127;
    int hq = q >> 7;
    float x1 = hq * STEP;
    float y1 = wq * STEP;
    float x2 = x1 + d_whw[k];
    float y2 = y1 + d_whh[k];
    float areaA = (x2 - x1) * (y2 - y1);

    float best = -1.0f;
    int bi = 0;
    #pragma unroll 4
    for (int i = 0; i < 64; i++) {
        float4 b = tg[i];
        float lx = fmaxf(b.x, x1), ly = fmaxf(b.y, y1);
        float rx = fminf(b.z, x2), ry = fminf(b.w, y2);
        float iw = fmaxf(rx - lx, 0.0f), ih = fmaxf(ry - ly, 0.0f);
        float inter = iw * ih;
        float at = (b.z - b.x) * (b.w - b.y);
        float iou = inter / (at + areaA - inter);
        if (iou > best) { best = iou; bi = i; }   // first-max == jnp.argmax
    }
    d_maxIou[a] = best;
    d_tgtIdx[a] = bi;

    // neg tie-class exactly as reference: value (1 - max_iou) rounds to 1.0f
    bool isz = (best < 0.3f) && ((1.0f - best) == 1.0f);
    bool isp = (best > 0.7f);
    unsigned zb = __ballot_sync(0xFFFFFFFFu, isz);
    unsigned pb = __ballot_sync(0xFFFFFFFFu, isp);
    int lane = t & 31, w = t >> 5;
    if (lane == 0) { wz[w] = __popc(zb); wp[w] = __popc(pb); }
    __syncthreads();
    if (t == 0) {
        int sz = 0, sp = 0;
        #pragma unroll
        for (int i = 0; i < 8; i++) { sz += wz[i]; sp += wp[i]; }
        d_zCnt[blockIdx.x] = sz;
        d_pCnt[blockIdx.x] = sp;
    }
}

// ---------------- scan block counts ----------------
__global__ void nscan_kernel() {
    __shared__ int s[1024];
    int t = threadIdx.x;
    int v = (t < NBLK) ? d_zCnt[t] : 0;
    s[t] = v; __syncthreads();
    for (int off = 1; off < 1024; off <<= 1) {
        int x = (t >= off) ? s[t - off] : 0;
        __syncthreads();
        s[t] += x;
        __syncthreads();
    }
    if (t < NBLK) d_zPrefix[t] = s[t] - v;
    __syncthreads();
    int v2 = (t < NBLK) ? d_pCnt[t] : 0;
    s[t] = v2; __syncthreads();
    for (int off = 1; off < 1024; off <<= 1) {
        int x = (t >= off) ? s[t - off] : 0;
        __syncthreads();
        s[t] += x;
        __syncthreads();
    }
    if (t < NBLK) d_pPrefix[t] = s[t] - v2;
    if (t == 1023) d_posTotal = s[1023];
}

// ---------------- rank-based selection write ----------------
__global__ void select_write() {
    __shared__ int zoff[8], poff[8];
    int t = threadIdx.x, lane = t & 31, w = t >> 5;
    int a = blockIdx.x * 256 + t;
    float best = d_maxIou[a];
    int tot = d_posTotal;
    int npos = tot < 128 ? tot : 128;
    int K = 256 - npos;
    bool z = (best < 0.3f) && ((1.0f - best) == 1.0f);
    bool p = (best > 0.7f) && (tot <= 128);
    unsigned zb = __ballot_sync(0xFFFFFFFFu, z);
    unsigned pb = __ballot_sync(0xFFFFFFFFu, p);
    if (lane == 0) { zoff[w] = __popc(zb); poff[w] = __popc(pb); }
    __syncthreads();
    int zpre = 0, ppre = 0;
    for (int i = 0; i < w; i++) { zpre += zoff[i]; ppre += poff[i]; }
    if (z) {
        int g = d_zPrefix[blockIdx.x] + zpre + __popc(zb & ((1u << lane) - 1));
        if (g < K) {
            d_negIdx[g] = a;
            int ss = (2 * a) & 16383;
            int cs = 36 + (a >> 13);
            d_colPos[768 + 2 * g] = ss;      d_colMeta[768 + 2 * g] = cs;
            d_colPos[768 + 2 * g + 1] = ss + 1; d_colMeta[768 + 2 * g + 1] = cs;
        }
    }
    if (p) {
        int g = d_pPrefix[blockIdx.x] + ppre + __popc(pb & ((1u << lane) - 1));
        d_posIdx[g] = a;   // g < tot <= 128
    }
}

__global__ void neg_fill() {   // 1 x 256
    int t = threadIdx.x;
    int tot = d_posTotal;
    int npos = tot < 128 ? tot : 128;
    int K = 256 - npos;
    if (t < K) {
        d_negValid[t] = 1;
    } else {
        d_negValid[t] = 0;
        d_negIdx[t] = 0;
        d_colPos[768 + 2 * t] = 0;      d_colMeta[768 + 2 * t] = 36;
        d_colPos[768 + 2 * t + 1] = 0;  d_colMeta[768 + 2 * t + 1] = 36;
    }
}

// ---------------- fallback sort helper ----------------
__device__ __forceinline__ void bitonic2048(unsigned long long* s) {
    int t = threadIdx.x;  // 1024 threads
    for (int k = 2; k <= 2048; k <<= 1) {
        for (int j = k >> 1; j > 0; j >>= 1) {
            __syncthreads();
            #pragma unroll
            for (int base = 0; base < 2048; base += 1024) {
                int i = base + t;
                int ixj = i ^ j;
                if (ixj > i) {
                    unsigned long long va = s[i], vb = s[ixj];
                    bool sw = ((i & k) == 0) ? (va < vb) : (va > vb);
                    if (sw) { s[i] = vb; s[ixj] = va; }
                }
            }
        }
    }
    __syncthreads();
}

// ---------------- positive finalize (1 x 1024) ----------------
__global__ void pos_finalize() {
    __shared__ unsigned long long s[2048];
    __shared__ int c;
    int t = threadIdx.x;
    int cnt = d_posTotal;
    int npos = cnt < 128 ? cnt : 128;
    if (t == 0) d_nPos = npos;
    if (cnt > 128) {
        // rare fallback: exact top-128 by (iou desc, index asc)
        s[t] = 0ULL; s[t + 1024] = 0ULL;
        if (t == 0) c = 0;
        __syncthreads();
        for (int a = t; a < A_TOT; a += 1024) {
            float b = d_maxIou[a];
            if (b > 0.7f) {
                int sl = atomicAdd(&c, 1);
                if (sl < 2048)
                    s[sl] = (((unsigned long long)__float_as_uint(b) << 32) |
                             (0xFFFFFFFFu - (unsigned)a));
            }
        }
        __syncthreads();
        bitonic2048(s);
        if (t < 128)
            d_posIdx[t] = (int)(0xFFFFFFFFu - (unsigned)(s[t] & 0xFFFFFFFFULL));
    }
    __syncthreads();
    if (t < 128) {
        int valid = (t < npos);
        int p = valid ? d_posIdx[t] : 0;
        d_posIdx[t] = p;
        d_posValid[t] = valid;
        int sb = (4 * p) & 16383;
        int ssc = (2 * p) & 16383;
        int cb = valid ? (p >> 12) : 0;
        int cs = valid ? (36 + (p >> 13)) : 36;
        #pragma unroll
        for (int e = 0; e < 4; e++) {
            d_colPos[4 * t + e] = valid ? (sb + e) : 0;
            d_colMeta[4 * t + e] = cb;
        }
        #pragma unroll
        for (int e = 0; e < 2; e++) {
            d_colPos[512 + 2 * t + e] = valid ? (ssc + e) : 0;
            d_colMeta[512 + 2 * t + e] = cs;
        }
    }
}

// ---------------- gather 3x3 input patches: Bg[k][n] ----------------
__global__ void gather_kernel(const float* __restrict__ x) {
    int idx = blockIdx.x * 256 + threadIdx.x;   // KTOT*NCOL threads
    int n = idx % NCOL;
    int k = idx / NCOL;
    int s = d_colPos[n];
    int ci = k / 9;
    int r  = k - ci * 9;
    int ky = r / 3;
    int kx = r - ky * 3;
    int y  = (s >> 7) + ky - 1;
    int xx = (s & 127) + kx - 1;
    float v = 0.0f;
    if (((unsigned)y < 128u) && ((unsigned)xx < 128u))
        v = x[ci * HW + y * GW + xx];
    d_Bg[idx] = v;
}

// ---------------- GEMM: partials, FFMA2, 64x64 tile / 64 threads / 8x8 regs ----------------
__global__ __launch_bounds__(64)
void gemm_kernel(const float* __restrict__ W) {
    __shared__ float2 As2[16][64];   // A duplicated pairs {v,v}, [k][m]
    __shared__ float  Bs[16][64];    // [k][n]
    int tid = threadIdx.x;
    int tx = tid & 7, ty = tid >> 3;
    int n0 = blockIdx.x * 64;
    int m0 = blockIdx.y * 64;
    int ks = blockIdx.z;
    int kbase = ks * KCH;

    const float* Ap = W + (m0 + tid) * KTOT + kbase;          // 16 consecutive k
    int bk = tid >> 2;
    int bn = (tid & 3) * 16;
    const float* Bp = d_Bg + (kbase + bk) * NCOL + n0 + bn;

    unsigned long long acc[8][4];
    #pragma unroll
    for (int i = 0; i < 8; i++)
        #pragma unroll
        for (int j = 0; j < 4; j++) acc[i][j] = 0ULL;

    for (int k0 = 0; k0 < KCH; k0 += 16) {
        float4 a0 = *(const float4*)(Ap + k0);
        float4 a1 = *(const float4*)(Ap + k0 + 4);
        float4 a2 = *(const float4*)(Ap + k0 + 8);
        float4 a3 = *(const float4*)(Ap + k0 + 12);
        const float* bp = Bp + k0 * NCOL;
        float4 b0 = *(const float4*)(bp);
        float4 b1 = *(const float4*)(bp + 4);
        float4 b2 = *(const float4*)(bp + 8);
        float4 b3 = *(const float4*)(bp + 12);
        __syncthreads();
        {
            float va[16] = {a0.x, a0.y, a0.z, a0.w, a1.x, a1.y, a1.z, a1.w,
                            a2.x, a2.y, a2.z, a2.w, a3.x, a3.y, a3.z, a3.w};
            #pragma unroll
            for (int j = 0; j < 16; j++) As2[j][tid] = make_float2(va[j], va[j]);
        }
        *(float4*)&Bs[bk][bn]      = b0;
        *(float4*)&Bs[bk][bn + 4]  = b1;
        *(float4*)&Bs[bk][bn + 8]  = b2;
        *(float4*)&Bs[bk][bn + 12] = b3;
        __syncthreads();
        #pragma unroll
        for (int kk = 0; kk < 16; kk++) {
            const ulonglong2* ar = (const ulonglong2*)(&As2[kk][ty * 8]);
            ulonglong2 A0 = ar[0], A1 = ar[1], A2 = ar[2], A3 = ar[3];
            const ulonglong2* br = (const ulonglong2*)(&Bs[kk][tx * 8]);
            ulonglong2 B0 = br[0], B1 = br[1];
            unsigned long long am[8] = {A0.x, A0.y, A1.x, A1.y,
                                        A2.x, A2.y, A3.x, A3.y};
            unsigned long long bv[4] = {B0.x, B0.y, B1.x, B1.y};
            #pragma unroll
            for (int mi = 0; mi < 8; mi++)
                #pragma unroll
                for (int nj = 0; nj < 4; nj++)
                    acc[mi][nj] = ffma2(am[mi], bv[nj], acc[mi][nj]);
        }
    }
    // transposed partial store: d_hp[ks][n][m]
    #pragma unroll
    for (int j = 0; j < 8; j++) {
        float v[8];
        #pragma unroll
        for (int mi = 0; mi < 8; mi++) {
            float2 pr = *(float2*)&acc[mi][j >> 1];
            v[mi] = (j & 1) ? pr.y : pr.x;
        }
        float4* o = (float4*)(d_hp + (ks * NCOL + n0 + tx * 8 + j) * CIN + m0 + ty * 8);
        o[0] = make_float4(v[0], v[1], v[2], v[3]);
        o[1] = make_float4(v[4], v[5], v[6], v[7]);
    }
}

// ---------------- reduce partials + bias + relu -> hT[n][c] ----------------
__global__ void hreduce_kernel(const float* __restrict__ bias) {
    int idx = blockIdx.x * 256 + threadIdx.x;   // NCOL*CIN
    int m = idx & (CIN - 1);
    float s = d_hp[idx] + d_hp[idx + NCOL * CIN] +
              d_hp[idx + 2 * NCOL * CIN] + d_hp[idx + 3 * NCOL * CIN];
    d_hT[idx] = fmaxf(s + bias[m], 0.0f);
}

// ---------------- per-column 1x1 conv dot (coalesced over c now) ----------------
__global__ void coldot_kernel(const float* __restrict__ bw, const float* __restrict__ bb,
                              const float* __restrict__ sw, const float* __restrict__ sb) {
    int col = blockIdx.x * 8 + (threadIdx.x >> 5);
    int lane = threadIdx.x & 31;
    int meta = d_colMeta[col];
    const float* w;
    float b;
    if (meta < 36) { w = bw + meta * 512; b = bb[meta]; }
    else           { w = sw + (meta - 36) * 512; b = sb[meta - 36]; }
    const float4* hv = (const float4*)(d_hT + col * CIN);
    const float4* wv = (const float4*)w;
    float s = 0.0f;
    #pragma unroll
    for (int i = lane; i < 128; i += 32) {
        float4 hh = hv[i], ww = wv[i];
        s += hh.x * ww.x + hh.y * ww.y + hh.z * ww.z + hh.w * ww.w;
    }
    #pragma unroll
    for (int o = 16; o > 0; o >>= 1) s += __shfl_xor_sync(0xFFFFFFFFu, s, o);
    if (lane == 0) d_val[col] = fmaxf(s + b, 0.0f);
}

// ---------------- loss ----------------
__global__ void loss_kernel(const float* __restrict__ target, float* __restrict__ out) {
    __shared__ float rce[256], rsl[256], rvc[256];
    int t = threadIdx.x;
    float ce = 0.0f, sl = 0.0f, vc = 0.0f;
    if (t < 128 && d_posValid[t]) {
        float s0 = d_val[512 + 2 * t], s1 = d_val[512 + 2 * t + 1];
        float m = fmaxf(s0, s1);
        float lse = m + logf(expf(s0 - m) + expf(s1 - m));
        ce += lse - s0;
        vc += 1.0f;
        int p = d_posIdx[t];
        int k = p % 9;
        int q = p / 9;
        int wq = q & 127;
        int hq = q >> 7;
        float ax1 = hq * STEP, ay1 = wq * STEP;
        float aw = d_whw[k], ah = d_whh[k];
        float acx = ax1 + aw * 0.5f, acy = ay1 + ah * 0.5f;
        float4 tb = ((const float4*)target)[d_tgtIdx[p]];
        float bw_ = tb.z - tb.x, bh_ = tb.w - tb.y;
        float bcx = tb.x + bw_ * 0.5f, bcy = tb.y + bh_ * 0.5f;
        float tr[4] = {(bcx - acx) / aw, (bcy - acy) / ah,
                       logf(bw_ / aw), logf(bh_ / ah)};
        #pragma unroll
        for (int e = 0; e < 4; e++) {
            float d = d_val[4 * t + e] - tr[e];
            float ad = fabsf(d);
            sl += (ad < 1.0f) ? 0.5f * d * d : (ad - 0.5f);
        }
    }
    if (t < 256 && d_negValid[t]) {
        float s0 = d_val[768 + 2 * t], s1 = d_val[768 + 2 * t + 1];
        float m = fmaxf(s0, s1);
        float lse = m + logf(expf(s0 - m) + expf(s1 - m));
        ce += lse - s1;
        vc += 1.0f;
    }
    rce[t] = ce; rsl[t] = sl; rvc[t] = vc;
    __syncthreads();
    for (int s2 = 128; s2 > 0; s2 >>= 1) {
        if (t < s2) { rce[t] += rce[t + s2]; rsl[t] += rsl[t + s2]; rvc[t] += rvc[t + s2]; }
        __syncthreads();
    }
    if (t == 0) {
        float np = (float)d_nPos;
        float score_loss = rce[0] / fmaxf(rvc[0], 1.0f);
        float reg_loss = rsl[0] / fmaxf(np * 4.0f, 1.0f);
        out[0] = score_loss + 10.0f * reg_loss;
    }
}

// ---------------- launch ----------------
extern "C" void kernel_launch(void* const* d_in, const int* in_sizes, int n_in,
                              void* d_out, int out_size) {
    const float* x       = (const float*)d_in[0];
    const float* target  = (const float*)d_in[1];
    const float* conv_w  = (const float*)d_in[2];
    const float* conv_b  = (const float*)d_in[3];
    const float* bbox_w  = (const float*)d_in[4];
    const float* bbox_b  = (const float*)d_in[5];
    const float* score_w = (const float*)d_in[6];
    const float* score_b = (const float*)d_in[7];
    float* out = (float*)d_out;

    iou_kernel<<<NBLK, 256>>>(target);
    nscan_kernel<<<1, 1024>>>();
    select_write<<<NBLK, 256>>>();
    neg_fill<<<1, 256>>>();
    pos_finalize<<<1, 1024>>>();
    gather_kernel<<<(KTOT * NCOL) / 256, 256>>>(x);
    gemm_kernel<<<dim3(NCOL / 64, CIN / 64, KSPLIT), 64>>>(conv_w);
    hreduce_kernel<<<(NCOL * CIN) / 256, 256>>>(conv_b);
    coldot_kernel<<<NCOL / 8, 256>>>(bbox_w, bbox_b, score_w, score_b);
    loss_kernel<<<1, 256>>>(target, out);
}

// round 7
// speedup vs baseline: 2.7271x; 1.2014x over previous
#include <cuda_runtime.h>
#include <cuda_bf16.h>
#include <math.h>

#define A_TOT 147456      // 128*128*9 anchors
#define HW    16384
#define GW    128
#define CIN   512
#define KTOT  4608        // 512*9
#define KSPLIT 8
#define KCH   576         // KTOT/KSPLIT
#define NCOL  1280        // original columns: 512 pos-bbox + 256 pos-score + 512 neg-score
#define NU2   1088        // max unique columns padded (513 + 4*128 -> 1025 -> 1088)
#define NBLK  576         // A_TOT/256
#define STEP  (2048.0f/127.0f)

__constant__ float d_whw[9] = {128.0f, 181.01933598375618f, 90.50966799187809f,
                               256.0f, 362.03867196751236f, 181.01933598375618f,
                               512.0f, 724.0773439350247f, 362.03867196751236f};
__constant__ float d_whh[9] = {128.0f, 90.50966799187809f, 181.01933598375618f,
                               256.0f, 181.01933598375618f, 362.03867196751236f,
                               512.0f, 362.03867196751236f, 724.0773439350247f};

// ---------------- static device scratch ----------------
__device__ float d_maxIou[A_TOT];
__device__ int   d_tgtIdx[A_TOT];
__device__ int   d_zCnt[NBLK];
__device__ int   d_pCnt[NBLK];
__device__ int   d_zPrefix[NBLK];
__device__ int   d_pPrefix[NBLK];
__device__ int   d_posTotal;
__device__ int   d_posIdx[128];
__device__ int   d_posValid[128];
__device__ int   d_negValid[256];
__device__ int   d_nPos;
__device__ int   d_Upad;              // padded unique-column count (multiple of 64)
__device__ int   d_colPos[NCOL];      // spatial position per ORIGINAL column (valid only)
__device__ int   d_colMeta[NCOL];     // weight row per original column (valid only)
__device__ int   d_uniqPos[NU2];      // spatial position per UNIQUE column
__device__ float d_Bg[KTOT * NU2];    // gathered patches [k][u]   (20.1 MB)
__device__ float d_hp[KSPLIT * NU2 * CIN]; // GEMM partials [ks][u][m] (17.8 MB)
__device__ float d_val[NCOL];

// ---------------- packed fp32 FMA ----------------
__device__ __forceinline__ unsigned long long ffma2(unsigned long long a,
                                                    unsigned long long b,
                                                    unsigned long long c) {
    unsigned long long d;
    asm("fma.rn.f32x2 %0, %1, %2, %3;" : "=l"(d) : "l"(a), "l"(b), "l"(c));
    return d;
}

// ---------------- phase A: IoU matching + per-block class counts ----------------
__global__ void iou_kernel(const float* __restrict__ target) {
    __shared__ float4 tg[64];
    __shared__ int wz[8], wp[8];
    int t = threadIdx.x;
    if (t < 64) tg[t] = ((const float4*)target)[t];
    __syncthreads();
    int a = blockIdx.x * 256 + t;
    int k = a % 9;
    int q = a / 9;
    int wq = q & 127;
    int hq = q >> 7;
    float x1 = hq * STEP;
    float y1 = wq * STEP;
    float x2 = x1 + d_whw[k];
    float y2 = y1 + d_whh[k];
    float areaA = (x2 - x1) * (y2 - y1);

    float best = -1.0f;
    int bi = 0;
    #pragma unroll 4
    for (int i = 0; i < 64; i++) {
        float4 b = tg[i];
        float lx = fmaxf(b.x, x1), ly = fmaxf(b.y, y1);
        float rx = fminf(b.z, x2), ry = fminf(b.w, y2);
        float iw = fmaxf(rx - lx, 0.0f), ih = fmaxf(ry - ly, 0.0f);
        float inter = iw * ih;
        float at = (b.z - b.x) * (b.w - b.y);
        float iou = inter / (at + areaA - inter);
        if (iou > best) { best = iou; bi = i; }   // first-max == jnp.argmax
    }
    d_maxIou[a] = best;
    d_tgtIdx[a] = bi;

    // neg tie-class exactly as reference: value (1 - max_iou) rounds to 1.0f
    bool isz = (best < 0.3f) && ((1.0f - best) == 1.0f);
    bool isp = (best > 0.7f);
    unsigned zb = __ballot_sync(0xFFFFFFFFu, isz);
    unsigned pb = __ballot_sync(0xFFFFFFFFu, isp);
    int lane = t & 31, w = t >> 5;
    if (lane == 0) { wz[w] = __popc(zb); wp[w] = __popc(pb); }
    __syncthreads();
    if (t == 0) {
        int sz = 0, sp = 0;
        #pragma unroll
        for (int i = 0; i < 8; i++) { sz += wz[i]; sp += wp[i]; }
        d_zCnt[blockIdx.x] = sz;
        d_pCnt[blockIdx.x] = sp;
    }
}

// ---------------- scan block counts ----------------
__global__ void nscan_kernel() {
    __shared__ int s[1024];
    int t = threadIdx.x;
    int v = (t < NBLK) ? d_zCnt[t] : 0;
    s[t] = v; __syncthreads();
    for (int off = 1; off < 1024; off <<= 1) {
        int x = (t >= off) ? s[t - off] : 0;
        __syncthreads();
        s[t] += x;
        __syncthreads();
    }
    if (t < NBLK) d_zPrefix[t] = s[t] - v;
    __syncthreads();
    int v2 = (t < NBLK) ? d_pCnt[t] : 0;
    s[t] = v2; __syncthreads();
    for (int off = 1; off < 1024; off <<= 1) {
        int x = (t >= off) ? s[t - off] : 0;
        __syncthreads();
        s[t] += x;
        __syncthreads();
    }
    if (t < NBLK) d_pPrefix[t] = s[t] - v2;
    if (t == 1023) d_posTotal = s[1023];
}

// ---------------- rank-based selection write ----------------
__global__ void select_write() {
    __shared__ int zoff[8], poff[8];
    int t = threadIdx.x, lane = t & 31, w = t >> 5;
    int a = blockIdx.x * 256 + t;
    float best = d_maxIou[a];
    int tot = d_posTotal;
    int npos = tot < 128 ? tot : 128;
    int K = 256 - npos;
    bool z = (best < 0.3f) && ((1.0f - best) == 1.0f);
    bool p = (best > 0.7f) && (tot <= 128);
    unsigned zb = __ballot_sync(0xFFFFFFFFu, z);
    unsigned pb = __ballot_sync(0xFFFFFFFFu, p);
    if (lane == 0) { zoff[w] = __popc(zb); poff[w] = __popc(pb); }
    __syncthreads();
    int zpre = 0, ppre = 0;
    for (int i = 0; i < w; i++) { zpre += zoff[i]; ppre += poff[i]; }
    if (z) {
        int g = d_zPrefix[blockIdx.x] + zpre + __popc(zb & ((1u << lane) - 1));
        if (g < K) {
            int ss = (2 * a) & 16383;
            int cs = 36 + (a >> 13);
            d_colPos[768 + 2 * g] = ss;         d_colMeta[768 + 2 * g] = cs;
            d_colPos[768 + 2 * g + 1] = ss + 1; d_colMeta[768 + 2 * g + 1] = cs;
        }
    }
    if (p) {
        int g = d_pPrefix[blockIdx.x] + ppre + __popc(pb & ((1u << lane) - 1));
        d_posIdx[g] = a;   // g < tot <= 128
    }
}

// ---------------- fallback sort helper ----------------
__device__ __forceinline__ void bitonic2048(unsigned long long* s) {
    int t = threadIdx.x;  // 1024 threads
    for (int k = 2; k <= 2048; k <<= 1) {
        for (int j = k >> 1; j > 0; j >>= 1) {
            __syncthreads();
            #pragma unroll
            for (int base = 0; base < 2048; base += 1024) {
                int i = base + t;
                int ixj = i ^ j;
                if (ixj > i) {
                    unsigned long long va = s[i], vb = s[ixj];
                    bool sw = ((i & k) == 0) ? (va < vb) : (va > vb);
                    if (sw) { s[i] = vb; s[ixj] = va; }
                }
            }
        }
    }
    __syncthreads();
}

// ---------------- finalize: pos cols + neg validity + unique-column table ----------------
__global__ void finalize_kernel() {
    __shared__ unsigned long long s[2048];
    __shared__ int c;
    int t = threadIdx.x;   // 1024 threads
    int cnt = d_posTotal;
    int npos = cnt < 128 ? cnt : 128;
    int K = 256 - npos;
    if (t == 0) {
        d_nPos = npos;
        int U = 513 + 4 * npos;
        d_Upad = (U + 63) & ~63;
    }
    if (cnt > 128) {
        // rare fallback: exact top-128 by (iou desc, index asc)
        s[t] = 0ULL; s[t + 1024] = 0ULL;
        if (t == 0) c = 0;
        __syncthreads();
        for (int a = t; a < A_TOT; a += 1024) {
            float b = d_maxIou[a];
            if (b > 0.7f) {
                int sl = atomicAdd(&c, 1);
                if (sl < 2048)
                    s[sl] = (((unsigned long long)__float_as_uint(b) << 32) |
                             (0xFFFFFFFFu - (unsigned)a));
            }
        }
        __syncthreads();
        bitonic2048(s);
        if (t < 128)
            d_posIdx[t] = (int)(0xFFFFFFFFu - (unsigned)(s[t] & 0xFFFFFFFFULL));
    }
    __syncthreads();
    if (t < 128) {
        int valid = (t < npos);
        d_posValid[t] = valid;
        if (valid) {
            int p = d_posIdx[t];
            int sb = (4 * p) & 16383;
            int ssc = (2 * p) & 16383;
            int cb = p >> 12;
            int cs = 36 + (p >> 13);
            #pragma unroll
            for (int e = 0; e < 4; e++) {
                d_colPos[4 * t + e] = sb + e;
                d_colMeta[4 * t + e] = cb;
            }
            #pragma unroll
            for (int e = 0; e < 2; e++) {
                d_colPos[512 + 2 * t + e] = ssc + e;
                d_colMeta[512 + 2 * t + e] = cs;
            }
        }
    }
    if (t < 256) d_negValid[t] = (t < K);
    __syncthreads();
    // build unique-position table: u=0 -> position 0 (shared by all invalid cols);
    // u>=1 -> valid columns in order (pos-bbox, pos-score, neg-score)
    for (int u = t; u < NU2; u += 1024) {
        int pos = 0;
        if (u >= 1) {
            int v = u - 1;
            if (v < 4 * npos)              pos = d_colPos[v];
            else if (v < 6 * npos)         pos = d_colPos[512 + (v - 4 * npos)];
            else if (v < 6 * npos + 2 * K) pos = d_colPos[768 + (v - 6 * npos)];
        }
        d_uniqPos[u] = pos;
    }
}

// ---------------- gather 3x3 input patches: Bg[k][u] (unique columns only) ----------------
__global__ void gather_kernel(const float* __restrict__ x) {
    int t = threadIdx.x;
    int n = blockIdx.x * 32 + (t & 31);     // grid.x = NU2/32 = 34
    int k = blockIdx.y * 8 + (t >> 5);      // grid.y = KTOT/8 = 576
    if (n >= d_Upad) return;
    int s = d_uniqPos[n];
    int ci = k / 9;
    int r  = k - ci * 9;
    int ky = r / 3;
    int kx = r - ky * 3;
    int y  = (s >> 7) + ky - 1;
    int xx = (s & 127) + kx - 1;
    float v = 0.0f;
    if (((unsigned)y < 128u) && ((unsigned)xx < 128u))
        v = x[ci * HW + y * GW + xx];
    d_Bg[k * NU2 + n] = v;
}

// ---------------- GEMM: partials, FFMA2, 64x64 tile / 64 threads / 8x8 regs ----------------
__global__ __launch_bounds__(64)
void gemm_kernel(const float* __restrict__ W) {
    int n0 = blockIdx.x * 64;
    if (n0 >= d_Upad) return;               // dedup early-exit (graph-safe, data-driven)
    __shared__ float2 As2[16][64];          // A duplicated pairs {v,v}, [k][m]
    __shared__ float  Bs[16][64];           // [k][n]
    int tid = threadIdx.x;
    int tx = tid & 7, ty = tid >> 3;
    int m0 = blockIdx.y * 64;
    int ks = blockIdx.z;
    int kbase = ks * KCH;

    const float* Ap = W + (m0 + tid) * KTOT + kbase;
    int bk = tid >> 2;
    int bn = (tid & 3) * 16;
    const float* Bp = d_Bg + (kbase + bk) * NU2 + n0 + bn;

    unsigned long long acc[8][4];
    #pragma unroll
    for (int i = 0; i < 8; i++)
        #pragma unroll
        for (int j = 0; j < 4; j++) acc[i][j] = 0ULL;

    for (int k0 = 0; k0 < KCH; k0 += 16) {
        float4 a0 = *(const float4*)(Ap + k0);
        float4 a1 = *(const float4*)(Ap + k0 + 4);
        float4 a2 = *(const float4*)(Ap + k0 + 8);
        float4 a3 = *(const float4*)(Ap + k0 + 12);
        const float* bp = Bp + k0 * NU2;
        float4 b0 = *(const float4*)(bp);
        float4 b1 = *(const float4*)(bp + 4);
        float4 b2 = *(const float4*)(bp + 8);
        float4 b3 = *(const float4*)(bp + 12);
        __syncthreads();
        {
            float va[16] = {a0.x, a0.y, a0.z, a0.w, a1.x, a1.y, a1.z, a1.w,
                            a2.x, a2.y, a2.z, a2.w, a3.x, a3.y, a3.z, a3.w};
            #pragma unroll
            for (int j = 0; j < 16; j++) As2[j][tid] = make_float2(va[j], va[j]);
        }
        *(float4*)&Bs[bk][bn]      = b0;
        *(float4*)&Bs[bk][bn + 4]  = b1;
        *(float4*)&Bs[bk][bn + 8]  = b2;
        *(float4*)&Bs[bk][bn + 12] = b3;
        __syncthreads();
        #pragma unroll
        for (int kk = 0; kk < 16; kk++) {
            const ulonglong2* ar = (const ulonglong2*)(&As2[kk][ty * 8]);
            ulonglong2 A0 = ar[0], A1 = ar[1], A2 = ar[2], A3 = ar[3];
            const ulonglong2* br = (const ulonglong2*)(&Bs[kk][tx * 8]);
            ulonglong2 B0 = br[0], B1 = br[1];
            unsigned long long am[8] = {A0.x, A0.y, A1.x, A1.y,
                                        A2.x, A2.y, A3.x, A3.y};
            unsigned long long bv[4] = {B0.x, B0.y, B1.x, B1.y};
            #pragma unroll
            for (int mi = 0; mi < 8; mi++)
                #pragma unroll
                for (int nj = 0; nj < 4; nj++)
                    acc[mi][nj] = ffma2(am[mi], bv[nj], acc[mi][nj]);
        }
    }
    // transposed partial store: d_hp[ks][u][m]
    #pragma unroll
    for (int j = 0; j < 8; j++) {
        float v[8];
        #pragma unroll
        for (int mi = 0; mi < 8; mi++) {
            float2 pr = *(float2*)&acc[mi][j >> 1];
            v[mi] = (j & 1) ? pr.y : pr.x;
        }
        float4* o = (float4*)(d_hp + (ks * NU2 + n0 + tx * 8 + j) * CIN + m0 + ty * 8);
        o[0] = make_float4(v[0], v[1], v[2], v[3]);
        o[1] = make_float4(v[4], v[5], v[6], v[7]);
    }
}

// ---------------- per-column 1x1 conv dot (fused partial-reduce + bias + relu) ----------------
__global__ void coldot_kernel(const float* __restrict__ bw, const float* __restrict__ bb,
                              const float* __restrict__ sw, const float* __restrict__ sb,
                              const float* __restrict__ conv_b) {
    int col = blockIdx.x * 8 + (threadIdx.x >> 5);
    int lane = threadIdx.x & 31;
    int npos = d_nPos;
    int u;
    if (col < 512)      { int t = col >> 2;         u = (t < npos) ? 1 + col : 0; }
    else if (col < 768) { int t = (col - 512) >> 1; u = (t < npos) ? 1 + 4 * npos + (col - 512) : 0; }
    else                { int g = (col - 768) >> 1; u = (g < 256 - npos) ? 1 + 6 * npos + (col - 768) : 0; }
    if (u == 0) return;   // invalid column: never read by the loss
    int meta = d_colMeta[col];
    const float* w;
    float b;
    if (meta < 36) { w = bw + meta * 512; b = bb[meta]; }
    else           { w = sw + (meta - 36) * 512; b = sb[meta - 36]; }
    const float4* wv = (const float4*)w;
    const float4* bias4 = (const float4*)conv_b;
    float s = 0.0f;
    for (int i = lane; i < 128; i += 32) {
        float4 a = bias4[i];
        #pragma unroll
        for (int ks = 0; ks < KSPLIT; ks++) {
            const float4* hp4 = (const float4*)(d_hp + (ks * NU2 + u) * CIN);
            float4 hv = hp4[i];
            a.x += hv.x; a.y += hv.y; a.z += hv.z; a.w += hv.w;
        }
        a.x = fmaxf(a.x, 0.0f); a.y = fmaxf(a.y, 0.0f);
        a.z = fmaxf(a.z, 0.0f); a.w = fmaxf(a.w, 0.0f);
        float4 ww = wv[i];
        s += a.x * ww.x + a.y * ww.y + a.z * ww.z + a.w * ww.w;
    }
    #pragma unroll
    for (int o = 16; o > 0; o >>= 1) s += __shfl_xor_sync(0xFFFFFFFFu, s, o);
    if (lane == 0) d_val[col] = fmaxf(s + b, 0.0f);
}

// ---------------- loss ----------------
__global__ void loss_kernel(const float* __restrict__ target, float* __restrict__ out) {
    __shared__ float rce[256], rsl[256], rvc[256];
    int t = threadIdx.x;
    float ce = 0.0f, sl = 0.0f, vc = 0.0f;
    if (t < 128 && d_posValid[t]) {
        float s0 = d_val[512 + 2 * t], s1 = d_val[512 + 2 * t + 1];
        float m = fmaxf(s0, s1);
        float lse = m + logf(expf(s0 - m) + expf(s1 - m));
        ce += lse - s0;
        vc += 1.0f;
        int p = d_posIdx[t];
        int k = p % 9;
        int q = p / 9;
        int wq = q & 127;
        int hq = q >> 7;
        float ax1 = hq * STEP, ay1 = wq * STEP;
        float aw = d_whw[k], ah = d_whh[k];
        float acx = ax1 + aw * 0.5f, acy = ay1 + ah * 0.5f;
        float4 tb = ((const float4*)target)[d_tgtIdx[p]];
        float bw_ = tb.z - tb.x, bh_ = tb.w - tb.y;
        float bcx = tb.x + bw_ * 0.5f, bcy = tb.y + bh_ * 0.5f;
        float tr[4] = {(bcx - acx) / aw, (bcy - acy) / ah,
                       logf(bw_ / aw), logf(bh_ / ah)};
        #pragma unroll
        for (int e = 0; e < 4; e++) {
            float d = d_val[4 * t + e] - tr[e];
            float ad = fabsf(d);
            sl += (ad < 1.0f) ? 0.5f * d * d : (ad - 0.5f);
        }
    }
    if (t < 256 && d_negValid[t]) {
        float s0 = d_val[768 + 2 * t], s1 = d_val[768 + 2 * t + 1];
        float m = fmaxf(s0, s1);
        float lse = m + logf(expf(s0 - m) + expf(s1 - m));
        ce += lse - s1;
        vc += 1.0f;
    }
    rce[t] = ce; rsl[t] = sl; rvc[t] = vc;
    __syncthreads();
    for (int s2 = 128; s2 > 0; s2 >>= 1) {
        if (t < s2) { rce[t] += rce[t + s2]; rsl[t] += rsl[t + s2]; rvc[t] += rvc[t + s2]; }
        __syncthreads();
    }
    if (t == 0) {
        float np = (float)d_nPos;
        float score_loss = rce[0] / fmaxf(rvc[0], 1.0f);
        float reg_loss = rsl[0] / fmaxf(np * 4.0f, 1.0f);
        out[0] = score_loss + 10.0f * reg_loss;
    }
}

// ---------------- launch ----------------
extern "C" void kernel_launch(void* const* d_in, const int* in_sizes, int n_in,
                              void* d_out, int out_size) {
    const float* x       = (const float*)d_in[0];
    const float* target  = (const float*)d_in[1];
    const float* conv_w  = (const float*)d_in[2];
    const float* conv_b  = (const float*)d_in[3];
    const float* bbox_w  = (const float*)d_in[4];
    const float* bbox_b  = (const float*)d_in[5];
    const float* score_w = (const float*)d_in[6];
    const float* score_b = (const float*)d_in[7];
    float* out = (float*)d_out;

    iou_kernel<<<NBLK, 256>>>(target);
    nscan_kernel<<<1, 1024>>>();
    select_write<<<NBLK, 256>>>();
    finalize_kernel<<<1, 1024>>>();
    gather_kernel<<<dim3(NU2 / 32, KTOT / 8), 256>>>(x);
    gemm_kernel<<<dim3(NU2 / 64, CIN / 64, KSPLIT), 64>>>(conv_w);
    coldot_kernel<<<NCOL / 8, 256>>>(bbox_w, bbox_b, score_w, score_b, conv_b);
    loss_kernel<<<1, 256>>>(target, out);
}